// round 10
// baseline (speedup 1.0000x reference)
#include <cuda_runtime.h>
#include <math.h>
#include <stdint.h>

#define B   64
#define TE  1024
#define DE  1024
#define DD  1024
#define H   1024

__device__ float g_Wa[B * H];        // Wa[b,h] = dec[b]·Wa_w[h] + Wa_b[h]
__device__ float g_scores[B * TE];   // partial scores -> softmax weights

__device__ __forceinline__ void cp16(uint32_t s, const void* g) {
    asm volatile("cp.async.cg.shared.global [%0], [%1], 16;"
                 :: "r"(s), "l"(__cvta_generic_to_global(g)) : "memory");
}
#define CP_COMMIT() asm volatile("cp.async.commit_group;" ::: "memory")
#define CP_WAIT2()  asm volatile("cp.async.wait_group 2;" ::: "memory")

__device__ __forceinline__ uint32_t smem_u32(const void* p) {
    uint32_t a;
    asm("{ .reg .u64 t; cvta.to.shared.u64 t, %1; cvt.u32.u64 %0, t; }" : "=r"(a) : "l"(p));
    return a;
}

// ---------------------------------------------------------------------------
// K0: zero partial-score accumulator
// ---------------------------------------------------------------------------
__global__ void zero_scores_kernel() {
    g_scores[blockIdx.x * 1024 + threadIdx.x] = 0.f;
}

// ---------------------------------------------------------------------------
// K1: Wa[b,h] = dec[b]·Wa_w[h] + Wa_b[h]
// 128 blocks x 8 h-rows, 256 thr = 8 h x 32 b-lanes.
// ---------------------------------------------------------------------------
__global__ void wa_kernel(const float* __restrict__ dec,
                          const float* __restrict__ Wa_w,
                          const float* __restrict__ Wa_b) {
    const int h0 = blockIdx.x * 8;
    const int tid = threadIdx.x;
    const int hl = tid >> 5;     // 0..7
    const int bl = tid & 31;     // 0..31

    __shared__ float sW[8][65];
    __shared__ float sD[64][65];

    float acc[2] = {0.f, 0.f};

    for (int d0 = 0; d0 < DD; d0 += 64) {
        __syncthreads();
        #pragma unroll
        for (int i = 0; i < 2; i++) {
            int l = tid + i * 256;
            if (l < 512) {
                int h = l >> 6, d = l & 63;
                sW[h][d] = Wa_w[(size_t)(h0 + h) * DD + d0 + d];
            }
        }
        #pragma unroll
        for (int i = 0; i < 16; i++) {
            int l = tid + i * 256;
            int b = l >> 6, d = l & 63;
            sD[b][d] = dec[(size_t)b * DD + d0 + d];
        }
        __syncthreads();
        #pragma unroll 8
        for (int d = 0; d < 64; d++) {
            float w = sW[hl][d];
            acc[0] += w * sD[bl][d];
            acc[1] += w * sD[bl + 32][d];
        }
    }
    float bias = Wa_b[h0 + hl];
    #pragma unroll
    for (int i = 0; i < 2; i++)
        g_Wa[(size_t)(bl + 32 * i) * H + h0 + hl] = acc[i] + bias;
}

// ---------------------------------------------------------------------------
// K2: fused Ua-GEMM (mma.sync tf32) + tanh + Va reduction  [R8 structure]
//   CTA tile: 256 e x 128 h, K=1024 in 32 chunks of 32.
//   8 warps as 4(m) x 2(n); warp tile m64 x n64.
//   4-stage cp.async pipeline, wait_group 2 (3-chunk prefetch slack),
//   one barrier per chunk, XOR-swizzled smem.
// ---------------------------------------------------------------------------
#define STG    49152
#define SB_OFF 32768
#define S_WAU  196608
#define S_VAW  197120
#define SC_SMEM 197632

__global__ __launch_bounds__(256, 1)
void score_kernel(const float* __restrict__ enc,
                  const float* __restrict__ Ua_w,
                  const float* __restrict__ Ua_b,
                  const float* __restrict__ Va_w) {
    extern __shared__ char sm[];
    const uint32_t smb = smem_u32(sm);

    const int tid  = threadIdx.x;
    const int wid  = tid >> 5;
    const int lane = tid & 31;
    const int wm = wid >> 1;      // warp rows: wm*64..+63 (of 256)
    const int wn = wid & 1;       // warp cols: wn*64..+63 (of 128)
    const int lq = lane >> 2;     // 0..7
    const int lr = lane & 3;      // 0..3

    const int b  = blockIdx.y >> 2;
    const int e0 = (blockIdx.y & 3) * 256;
    const int h0 = blockIdx.x * 128;

    const char* gA = (const char*)(enc  + ((size_t)b * TE + e0) * DE);
    const char* gB = (const char*)(Ua_w + (size_t)h0 * DE);

    const int r0   = tid >> 3;             // 0..31
    const int ci16 = (tid & 7) * 16;       // byte chunk in 128B row
    const uint32_t cswz = (uint32_t)ci16 ^ (uint32_t)((r0 & 7) * 16);

    uint32_t aoff[8], boff[4];
    #pragma unroll
    for (int i = 0; i < 8; i++) aoff[i] = (uint32_t)(r0 + 32 * i) * 128 + cswz;
    #pragma unroll
    for (int i = 0; i < 4; i++) boff[i] = SB_OFF + (uint32_t)(r0 + 32 * i) * 128 + cswz;

    const char* gAt = gA + (size_t)r0 * 4096 + ci16;
    const char* gBt = gB + (size_t)r0 * 4096 + ci16;

    // prologue: chunks 0..2 -> stages 0..2
    #pragma unroll
    for (int s = 0; s < 3; s++) {
        const uint32_t base = smb + (uint32_t)s * STG;
        const size_t go = (size_t)s * 128;
        #pragma unroll
        for (int i = 0; i < 8; i++) cp16(base + aoff[i], gAt + (size_t)i * 32 * 4096 + go);
        #pragma unroll
        for (int i = 0; i < 4; i++) cp16(base + boff[i], gBt + (size_t)i * 32 * 4096 + go);
        CP_COMMIT();
    }

    float acc[4][8][4];
    #pragma unroll
    for (int m = 0; m < 4; m++)
        #pragma unroll
        for (int n = 0; n < 8; n++)
            #pragma unroll
            for (int r = 0; r < 4; r++)
                acc[m][n][r] = 0.f;

    const uint32_t lqx = (uint32_t)(lq << 2);

    for (int c = 0; c < 32; c++) {
        CP_WAIT2();            // chunk c landed (issued 3 chunks ago)
        __syncthreads();       // visibility; compute(c-1) drained
        if (c + 3 < 32) {      // prefetch into stage (c+3)&3 (freed last iter)
            const uint32_t base = smb + (uint32_t)((c + 3) & 3) * STG;
            const size_t go = (size_t)(c + 3) * 128;
            #pragma unroll
            for (int i = 0; i < 8; i++) cp16(base + aoff[i], gAt + (size_t)i * 32 * 4096 + go);
            #pragma unroll
            for (int i = 0; i < 4; i++) cp16(base + boff[i], gBt + (size_t)i * 32 * 4096 + go);
        }
        CP_COMMIT();

        const uint32_t* Aw = (const uint32_t*)(sm + (size_t)(c & 3) * STG);
        const uint32_t* Bw = (const uint32_t*)(sm + (size_t)(c & 3) * STG + SB_OFF);

        #pragma unroll
        for (int k0 = 0; k0 < 32; k0 += 8) {
            const uint32_t kx0 = ((uint32_t)(k0 + lr))     ^ lqx;
            const uint32_t kx1 = ((uint32_t)(k0 + lr + 4)) ^ lqx;
            uint32_t a[4][4], bb[8][2];
            #pragma unroll
            for (int m = 0; m < 4; m++) {
                const uint32_t r1 = (uint32_t)(wm * 64 + m * 16 + lq) * 32;
                a[m][0] = Aw[r1 + kx0];
                a[m][1] = Aw[r1 + 256 + kx0];
                a[m][2] = Aw[r1 + kx1];
                a[m][3] = Aw[r1 + 256 + kx1];
            }
            #pragma unroll
            for (int n = 0; n < 8; n++) {
                const uint32_t br = (uint32_t)(wn * 64 + n * 8 + lq) * 32;
                bb[n][0] = Bw[br + kx0];
                bb[n][1] = Bw[br + kx1];
            }
            #pragma unroll
            for (int m = 0; m < 4; m++)
                #pragma unroll
                for (int n = 0; n < 8; n++)
                    asm volatile(
                        "mma.sync.aligned.m16n8k8.row.col.f32.tf32.tf32.f32 "
                        "{%0,%1,%2,%3}, {%4,%5,%6,%7}, {%8,%9}, {%0,%1,%2,%3};\n"
                        : "+f"(acc[m][n][0]), "+f"(acc[m][n][1]),
                          "+f"(acc[m][n][2]), "+f"(acc[m][n][3])
                        : "r"(a[m][0]), "r"(a[m][1]), "r"(a[m][2]), "r"(a[m][3]),
                          "r"(bb[n][0]), "r"(bb[n][1]));
        }
    }

    // stage wau/vaw for this h-block
    if (tid < 128) {
        ((float*)(sm + S_WAU))[tid] = g_Wa[(size_t)b * H + h0 + tid] + Ua_b[h0 + tid];
        ((float*)(sm + S_VAW))[tid] = Va_w[h0 + tid];
    }
    __syncthreads();
    const float* wau = (const float*)(sm + S_WAU);
    const float* vaw = (const float*)(sm + S_VAW);

    // epilogue: tanh + Va-weighted reduce -> per-row partial scores
    #pragma unroll
    for (int m = 0; m < 4; m++) {
        float rs[2] = {0.f, 0.f};
        #pragma unroll
        for (int n = 0; n < 8; n++)
            #pragma unroll
            for (int r = 0; r < 4; r++) {
                int h = wn * 64 + n * 8 + 2 * lr + (r & 1);
                rs[r >> 1] += vaw[h] * tanhf(acc[m][n][r] + wau[h]);
            }
        #pragma unroll
        for (int rr = 0; rr < 2; rr++) {
            float s = rs[rr];
            s += __shfl_xor_sync(0xffffffffu, s, 1);
            s += __shfl_xor_sync(0xffffffffu, s, 2);
            if (lr == 0) {
                int e = e0 + wm * 64 + m * 16 + rr * 8 + lq;
                atomicAdd(&g_scores[(size_t)b * TE + e], s);
            }
        }
    }
}

// ---------------------------------------------------------------------------
// K3: softmax over Te per batch (Va_b omitted: softmax shift-invariant)
// ---------------------------------------------------------------------------
__global__ void softmax_kernel() {
    const int b = blockIdx.x;
    const int tid = threadIdx.x;
    float* row = g_scores + (size_t)b * TE;
    __shared__ float red[256];

    float m = -1e30f;
    #pragma unroll
    for (int i = 0; i < 4; i++) m = fmaxf(m, row[tid + i * 256]);
    red[tid] = m;
    __syncthreads();
    for (int s = 128; s > 0; s >>= 1) {
        if (tid < s) red[tid] = fmaxf(red[tid], red[tid + s]);
        __syncthreads();
    }
    float M = red[0];
    __syncthreads();

    float vals[4];
    float sum = 0.f;
    #pragma unroll
    for (int i = 0; i < 4; i++) {
        vals[i] = expf(row[tid + i * 256] - M);
        sum += vals[i];
    }
    red[tid] = sum;
    __syncthreads();
    for (int s = 128; s > 0; s >>= 1) {
        if (tid < s) red[tid] += red[tid + s];
        __syncthreads();
    }
    float inv = 1.f / red[0];
    #pragma unroll
    for (int i = 0; i < 4; i++) row[tid + i * 256] = vals[i] * inv;
}

// ---------------------------------------------------------------------------
// K4: context[b,d] = sum_e w[b,e] * enc[b,e,d]
// grid (B, 4 d-quarters); each thread owns ONE output d over all 1024 e.
// No atomics, no zeroing: every output written exactly once.
// ---------------------------------------------------------------------------
__global__ void context_kernel(const float* __restrict__ enc,
                               float* __restrict__ out) {
    const int b  = blockIdx.x;
    const int dq = blockIdx.y;
    const int tid = threadIdx.x;

    __shared__ float ws[TE];
    #pragma unroll
    for (int i = 0; i < 4; i++)
        ws[tid + i * 256] = g_scores[(size_t)b * TE + tid + i * 256];
    __syncthreads();

    const int d = dq * 256 + tid;
    const float* eb = enc + (size_t)b * TE * DE + d;
    float acc = 0.f;
    #pragma unroll 8
    for (int e = 0; e < TE; e++)
        acc += ws[e] * eb[(size_t)e * DE];
    out[(size_t)b * DE + d] = acc;
}

// ---------------------------------------------------------------------------
extern "C" void kernel_launch(void* const* d_in, const int* in_sizes, int n_in,
                              void* d_out, int out_size) {
    const float* enc  = (const float*)d_in[0];
    const float* dec  = (const float*)d_in[1];
    const float* Wa_w = (const float*)d_in[2];
    const float* Wa_b = (const float*)d_in[3];
    const float* Ua_w = (const float*)d_in[4];
    const float* Ua_b = (const float*)d_in[5];
    const float* Va_w = (const float*)d_in[6];
    float* out = (float*)d_out;

    cudaFuncSetAttribute(score_kernel, cudaFuncAttributeMaxDynamicSharedMemorySize, SC_SMEM);

    zero_scores_kernel<<<64, 1024>>>();
    wa_kernel<<<128, 256>>>(dec, Wa_w, Wa_b);
    score_kernel<<<dim3(H / 128, B * TE / 256), 256, SC_SMEM>>>(enc, Ua_w, Ua_b, Va_w);
    softmax_kernel<<<B, 256>>>();
    context_kernel<<<dim3(B, 4), 256>>>(enc, out);
}

// round 11
// speedup vs baseline: 1.1573x; 1.1573x over previous
#include <cuda_runtime.h>
#include <math.h>
#include <stdint.h>

#define B   64
#define TE  1024
#define DE  1024
#define DD  1024
#define H   1024

__device__ float g_Wa[B * H];        // Wa[b,h] = dec[b]·Wa_w[h] + Wa_b[h]
__device__ float g_scores[B * TE];   // partial scores -> softmax weights

__device__ __forceinline__ void cp16(uint32_t s, const void* g) {
    asm volatile("cp.async.cg.shared.global [%0], [%1], 16;"
                 :: "r"(s), "l"(__cvta_generic_to_global(g)) : "memory");
}
#define CP_COMMIT() asm volatile("cp.async.commit_group;" ::: "memory")
#define CP_WAIT1()  asm volatile("cp.async.wait_group 1;" ::: "memory")

__device__ __forceinline__ uint32_t smem_u32(const void* p) {
    uint32_t a;
    asm("{ .reg .u64 t; cvta.to.shared.u64 t, %1; cvt.u32.u64 %0, t; }" : "=r"(a) : "l"(p));
    return a;
}

// ---------------------------------------------------------------------------
// K0: zero partial-score accumulator
// ---------------------------------------------------------------------------
__global__ void zero_scores_kernel() {
    g_scores[blockIdx.x * 1024 + threadIdx.x] = 0.f;
}

// ---------------------------------------------------------------------------
// K1: Wa[b,h] = dec[b]·Wa_w[h] + Wa_b[h]   [R8-measured version]
// ---------------------------------------------------------------------------
__global__ void wa_kernel(const float* __restrict__ dec,
                          const float* __restrict__ Wa_w,
                          const float* __restrict__ Wa_b) {
    const int h0 = blockIdx.x * 16;
    const int tid = threadIdx.x;
    const int hl = tid >> 4;
    const int bl = tid & 15;

    __shared__ float sW[16][65];
    __shared__ float sD[64][65];

    float acc[4] = {0.f, 0.f, 0.f, 0.f};

    for (int d0 = 0; d0 < DD; d0 += 64) {
        __syncthreads();
        #pragma unroll
        for (int i = 0; i < 4; i++) {
            int l = tid + i * 256;
            int h = l >> 6, d = l & 63;
            sW[h][d] = Wa_w[(size_t)(h0 + h) * DD + d0 + d];
        }
        #pragma unroll
        for (int i = 0; i < 16; i++) {
            int l = tid + i * 256;
            int b = l >> 6, d = l & 63;
            sD[b][d] = dec[(size_t)b * DD + d0 + d];
        }
        __syncthreads();
        #pragma unroll 8
        for (int d = 0; d < 64; d++) {
            float w = sW[hl][d];
            #pragma unroll
            for (int i = 0; i < 4; i++)
                acc[i] += w * sD[bl + 16 * i][d];
        }
    }
    float bias = Wa_b[h0 + hl];
    #pragma unroll
    for (int i = 0; i < 4; i++)
        g_Wa[(size_t)(bl + 16 * i) * H + h0 + hl] = acc[i] + bias;
}

// ---------------------------------------------------------------------------
// K2: fused Ua-GEMM (mma.sync tf32) + tanh + Va reduction
//   CTA tile: 128 e x 128 h, K=1024 in 32 chunks of 32.
//   4 warps (128 thr) as 2(m) x 2(n); warp tile m64 x n64.
//   3-stage cp.async pipeline (stage 32KB, total 97KB) -> 2 CTAs/SM:
//   co-resident CTA hides the per-chunk barrier/wait bubbles.
// ---------------------------------------------------------------------------
#define STG    32768
#define SB_OFF 16384
#define S_WAU  98304
#define S_VAW  98816
#define SC_SMEM 99328

__global__ __launch_bounds__(128, 2)
void score_kernel(const float* __restrict__ enc,
                  const float* __restrict__ Ua_w,
                  const float* __restrict__ Ua_b,
                  const float* __restrict__ Va_w) {
    extern __shared__ char sm[];
    const uint32_t smb = smem_u32(sm);

    const int tid  = threadIdx.x;
    const int wid  = tid >> 5;
    const int lane = tid & 31;
    const int wm = wid >> 1;      // warp rows: wm*64..+63 (of 128)
    const int wn = wid & 1;       // warp cols: wn*64..+63 (of 128)
    const int lq = lane >> 2;     // 0..7
    const int lr = lane & 3;      // 0..3

    const int b  = blockIdx.y >> 3;
    const int e0 = (blockIdx.y & 7) * 128;
    const int h0 = blockIdx.x * 128;

    const char* gA = (const char*)(enc  + ((size_t)b * TE + e0) * DE);
    const char* gB = (const char*)(Ua_w + (size_t)h0 * DE);

    // 128 threads; A and B each: 128 rows x 8 16B-chunks = 1024 units, 8/thread
    const int r0   = tid >> 3;             // 0..15
    const int ci16 = (tid & 7) * 16;
    const uint32_t cswz = (uint32_t)ci16 ^ (uint32_t)((r0 & 7) * 16);

    uint32_t aoff[8], boff[8];
    #pragma unroll
    for (int i = 0; i < 8; i++) {
        aoff[i] = (uint32_t)(r0 + 16 * i) * 128 + cswz;
        boff[i] = SB_OFF + aoff[i];
    }

    const char* gAt = gA + (size_t)r0 * 4096 + ci16;
    const char* gBt = gB + (size_t)r0 * 4096 + ci16;

    // prologue: chunks 0,1 -> stages 0,1
    #pragma unroll
    for (int s = 0; s < 2; s++) {
        const uint32_t base = smb + (uint32_t)s * STG;
        const size_t go = (size_t)s * 128;
        #pragma unroll
        for (int i = 0; i < 8; i++) {
            cp16(base + aoff[i], gAt + (size_t)i * 16 * 4096 + go);
            cp16(base + boff[i], gBt + (size_t)i * 16 * 4096 + go);
        }
        CP_COMMIT();
    }

    float acc[4][8][4];
    #pragma unroll
    for (int m = 0; m < 4; m++)
        #pragma unroll
        for (int n = 0; n < 8; n++)
            #pragma unroll
            for (int r = 0; r < 4; r++)
                acc[m][n][r] = 0.f;

    const uint32_t lqx = (uint32_t)(lq << 2);

    int stage = 0;                 // stage holding chunk c
    for (int c = 0; c < 32; c++) {
        CP_WAIT1();            // chunk c landed (c+1 may be in flight)
        __syncthreads();       // visibility; compute(c-1) drained
        if (c + 2 < 32) {      // prefetch c+2 into stage (stage+2)%3 (freed)
            int ps = stage + 2; if (ps >= 3) ps -= 3;
            const uint32_t base = smb + (uint32_t)ps * STG;
            const size_t go = (size_t)(c + 2) * 128;
            #pragma unroll
            for (int i = 0; i < 8; i++) {
                cp16(base + aoff[i], gAt + (size_t)i * 16 * 4096 + go);
                cp16(base + boff[i], gBt + (size_t)i * 16 * 4096 + go);
            }
        }
        CP_COMMIT();

        const uint32_t* Aw = (const uint32_t*)(sm + (size_t)stage * STG);
        const uint32_t* Bw = (const uint32_t*)(sm + (size_t)stage * STG + SB_OFF);

        #pragma unroll
        for (int k0 = 0; k0 < 32; k0 += 8) {
            const uint32_t kx0 = ((uint32_t)(k0 + lr))     ^ lqx;
            const uint32_t kx1 = ((uint32_t)(k0 + lr + 4)) ^ lqx;
            uint32_t a[4][4], bb[8][2];
            #pragma unroll
            for (int m = 0; m < 4; m++) {
                const uint32_t r1 = (uint32_t)(wm * 64 + m * 16 + lq) * 32;
                a[m][0] = Aw[r1 + kx0];
                a[m][1] = Aw[r1 + 256 + kx0];
                a[m][2] = Aw[r1 + kx1];
                a[m][3] = Aw[r1 + 256 + kx1];
            }
            #pragma unroll
            for (int n = 0; n < 8; n++) {
                const uint32_t br = (uint32_t)(wn * 64 + n * 8 + lq) * 32;
                bb[n][0] = Bw[br + kx0];
                bb[n][1] = Bw[br + kx1];
            }
            #pragma unroll
            for (int m = 0; m < 4; m++)
                #pragma unroll
                for (int n = 0; n < 8; n++)
                    asm volatile(
                        "mma.sync.aligned.m16n8k8.row.col.f32.tf32.tf32.f32 "
                        "{%0,%1,%2,%3}, {%4,%5,%6,%7}, {%8,%9}, {%0,%1,%2,%3};\n"
                        : "+f"(acc[m][n][0]), "+f"(acc[m][n][1]),
                          "+f"(acc[m][n][2]), "+f"(acc[m][n][3])
                        : "r"(a[m][0]), "r"(a[m][1]), "r"(a[m][2]), "r"(a[m][3]),
                          "r"(bb[n][0]), "r"(bb[n][1]));
        }
        if (++stage >= 3) stage = 0;
    }

    // stage wau/vaw for this h-block
    ((float*)(sm + S_WAU))[tid] = g_Wa[(size_t)b * H + h0 + tid] + Ua_b[h0 + tid];
    ((float*)(sm + S_VAW))[tid] = Va_w[h0 + tid];
    __syncthreads();
    const float* wau = (const float*)(sm + S_WAU);
    const float* vaw = (const float*)(sm + S_VAW);

    // epilogue: tanh + Va-weighted reduce -> per-row partial scores
    #pragma unroll
    for (int m = 0; m < 4; m++) {
        float rs[2] = {0.f, 0.f};
        #pragma unroll
        for (int n = 0; n < 8; n++)
            #pragma unroll
            for (int r = 0; r < 4; r++) {
                int h = wn * 64 + n * 8 + 2 * lr + (r & 1);
                rs[r >> 1] += vaw[h] * tanhf(acc[m][n][r] + wau[h]);
            }
        #pragma unroll
        for (int rr = 0; rr < 2; rr++) {
            float s = rs[rr];
            s += __shfl_xor_sync(0xffffffffu, s, 1);
            s += __shfl_xor_sync(0xffffffffu, s, 2);
            if (lr == 0) {
                int e = e0 + wm * 64 + m * 16 + rr * 8 + lq;
                atomicAdd(&g_scores[(size_t)b * TE + e], s);
            }
        }
    }
}

// ---------------------------------------------------------------------------
// K3: softmax over Te per batch (Va_b omitted: softmax shift-invariant)
// ---------------------------------------------------------------------------
__global__ void softmax_kernel() {
    const int b = blockIdx.x;
    const int tid = threadIdx.x;
    float* row = g_scores + (size_t)b * TE;
    __shared__ float red[256];

    float m = -1e30f;
    #pragma unroll
    for (int i = 0; i < 4; i++) m = fmaxf(m, row[tid + i * 256]);
    red[tid] = m;
    __syncthreads();
    for (int s = 128; s > 0; s >>= 1) {
        if (tid < s) red[tid] = fmaxf(red[tid], red[tid + s]);
        __syncthreads();
    }
    float M = red[0];
    __syncthreads();

    float vals[4];
    float sum = 0.f;
    #pragma unroll
    for (int i = 0; i < 4; i++) {
        vals[i] = expf(row[tid + i * 256] - M);
        sum += vals[i];
    }
    red[tid] = sum;
    __syncthreads();
    for (int s = 128; s > 0; s >>= 1) {
        if (tid < s) red[tid] += red[tid + s];
        __syncthreads();
    }
    float inv = 1.f / red[0];
    #pragma unroll
    for (int i = 0; i < 4; i++) row[tid + i * 256] = vals[i] * inv;
}

// ---------------------------------------------------------------------------
// K4: context[b,d] = sum_e w[b,e] * enc[b,e,d]   [R8-measured version]
// ---------------------------------------------------------------------------
__global__ void zero_kernel(float* __restrict__ out) {
    out[blockIdx.x * 256 + threadIdx.x] = 0.f;
}

__global__ void context_kernel(const float* __restrict__ enc,
                               float* __restrict__ out) {
    const int b  = blockIdx.x;
    const int ec = blockIdx.y;
    const int tid = threadIdx.x;

    __shared__ float ws[128];
    if (tid < 128) ws[tid] = g_scores[(size_t)b * TE + ec * 128 + tid];
    __syncthreads();

    const float* eb = enc + (size_t)b * TE * DE + (size_t)ec * 128 * DE;
    float acc[4] = {0.f, 0.f, 0.f, 0.f};
    for (int e = 0; e < 128; e++) {
        float we = ws[e];
        #pragma unroll
        for (int i = 0; i < 4; i++)
            acc[i] += we * eb[(size_t)e * DE + tid + i * 256];
    }
    #pragma unroll
    for (int i = 0; i < 4; i++)
        atomicAdd(&out[(size_t)b * DE + tid + i * 256], acc[i]);
}

// ---------------------------------------------------------------------------
extern "C" void kernel_launch(void* const* d_in, const int* in_sizes, int n_in,
                              void* d_out, int out_size) {
    const float* enc  = (const float*)d_in[0];
    const float* dec  = (const float*)d_in[1];
    const float* Wa_w = (const float*)d_in[2];
    const float* Wa_b = (const float*)d_in[3];
    const float* Ua_w = (const float*)d_in[4];
    const float* Ua_b = (const float*)d_in[5];
    const float* Va_w = (const float*)d_in[6];
    float* out = (float*)d_out;

    cudaFuncSetAttribute(score_kernel, cudaFuncAttributeMaxDynamicSharedMemorySize, SC_SMEM);

    zero_scores_kernel<<<64, 1024>>>();
    wa_kernel<<<64, 256>>>(dec, Wa_w, Wa_b);
    score_kernel<<<dim3(H / 128, B * TE / 128), 128, SC_SMEM>>>(enc, Ua_w, Ua_b, Va_w);
    softmax_kernel<<<B, 256>>>();
    zero_kernel<<<(B * DE) / 256, 256>>>(out);
    context_kernel<<<dim3(B, 8), 256>>>(enc, out);
}